// round 16
// baseline (speedup 1.0000x reference)
#include <cuda_runtime.h>
#include <math.h>

#define B_   16
#define N_   8192
#define S_   1024
#define K_   32
#define G_   (B_*S_)            // 16384 groups
#define BSK  (G_*K_)            // 524288 rows

typedef unsigned long long ull;

// ---------------- device scratch (no allocations allowed) ----------------
__device__ double g_sum[3][128];
__device__ double g_sq[3][128];
__device__ float  g_af[3][128];
__device__ float  g_shf[3][128];
__device__ int    g_ball[BSK];
__device__ __align__(16) float4 g_xyzw[B_*N_];         // {x,y,z,|p|^2} 2 MB
__device__ __align__(16) float g_y2[(size_t)BSK*64];   // 128 MB
__device__ __align__(16) float g_gmax[(size_t)G_*128]; // 8 MB
__device__ __align__(16) float g_gmin[(size_t)G_*128]; // 8 MB

// ---------------- f32x2 packed helpers (IEEE .rn per lane) ---------------
__device__ __forceinline__ ull pack2(float lo, float hi) {
    ull r;
    asm("mov.b64 %0, {%1, %2};" : "=l"(r) : "f"(lo), "f"(hi));
    return r;
}
__device__ __forceinline__ void fma2(ull& d, ull a, ull b) {
    asm("fma.rn.f32x2 %0, %1, %2, %0;" : "+l"(d) : "l"(a), "l"(b));
}
__device__ __forceinline__ ull add2(ull a, ull b) {
    ull r;
    asm("add.rn.f32x2 %0, %1, %2;" : "=l"(r) : "l"(a), "l"(b));
    return r;
}
__device__ __forceinline__ ull mul2(ull a, ull b) {
    ull r;
    asm("mul.rn.f32x2 %0, %1, %2;" : "=l"(r) : "l"(a), "l"(b));
    return r;
}
__device__ __forceinline__ float2 unpack2(ull v) {
    float lo, hi;
    asm("mov.b64 {%0, %1}, %2;" : "=f"(lo), "=f"(hi) : "l"(v));
    return make_float2(lo, hi);
}

// ---------------- zero the stat accumulators (graph replay safe) ---------
__global__ void zero_stats_kernel() {
    int i = blockIdx.x * blockDim.x + threadIdx.x;
    if (i < 3*128) {
        ((double*)g_sum)[i] = 0.0;
        ((double*)g_sq)[i]  = 0.0;
    }
}

// ---------------- prep: pack {x,y,z,pp} per point ------------------------
__global__ void prep_kernel(const float* __restrict__ xyz) {
    int i = blockIdx.x * blockDim.x + threadIdx.x;    // over B_*N_
    float x = xyz[3*i], y = xyz[3*i+1], z = xyz[3*i+2];
    float pp = __fmaf_rn(x, x, __fmaf_rn(y, y, z*z)); // identical to ball's old pp
    g_xyzw[i] = make_float4(x, y, z, pp);
}

// ---------------- FPS: x-sorted points + 16 warp-slabs, pruning ----------
#define FPS_T 512
#define FPS_W 16
#define FPS_SMEM_BYTES ((3*N_ + S_ + 64 + 256) * 4)

__global__ __launch_bounds__(FPS_T, 1)
void fps_kernel(const float* __restrict__ xyz, float* __restrict__ out_xyz) {
    extern __shared__ float smf[];
    float*    ssx     = smf;
    float*    ssy     = ssx + N_;
    float*    ssz     = ssy + N_;
    int*      scent   = (int*)(ssz + N_);          // [1024]
    unsigned* cb_bits = (unsigned*)(scent + S_);   // [2][16]
    int*      cb_idx  = (int*)(cb_bits + 32);      // [2][16]
    int*      hist    = (int*)(cb_idx + 32);       // [256]

    const int b = blockIdx.x, t = threadIdx.x;
    const int lane = t & 31;
    const int warp = t >> 5;
    const float* xb = xyz + (size_t)b * N_ * 3;

    // ---- counting sort by x (256 buckets) ----
    if (t < 256) hist[t] = 0;
    __syncthreads();
#pragma unroll 4
    for (int k = 0; k < 16; k++) {
        int p = 16*t + k;
        float x = xb[3*p];
        int bk = min((int)(x * 256.0f), 255);
        atomicAdd(&hist[bk], 1);
    }
    __syncthreads();
    if (t == 0) {
        int acc = 0;
        for (int i = 0; i < 256; i++) { int h = hist[i]; hist[i] = acc; acc += h; }
    }
    __syncthreads();
#pragma unroll 4
    for (int k = 0; k < 16; k++) {
        int p = 16*t + k;
        float x = xb[3*p], y = xb[3*p+1], z = xb[3*p+2];
        int bk = min((int)(x * 256.0f), 255);
        int pos = atomicAdd(&hist[bk], 1);
        ssx[pos] = x; ssy[pos] = y; ssz[pos] = z;
        if (p == 0) scent[0] = pos;
    }
    __syncthreads();

    ull pxp[8], pyp[8], pzp[8];
    float dist[16];
    float mxlo = 1e30f, mxhi = -1e30f;
#pragma unroll
    for (int i = 0; i < 8; i++) {
        int p = 16*t + 2*i;
        float x0 = ssx[p], x1 = ssx[p+1];
        pxp[i] = pack2(x0, x1);
        pyp[i] = pack2(ssy[p], ssy[p+1]);
        pzp[i] = pack2(ssz[p], ssz[p+1]);
        mxlo = fminf(mxlo, fminf(x0, x1));
        mxhi = fmaxf(mxhi, fmaxf(x0, x1));
        dist[2*i] = 1e10f; dist[2*i+1] = 1e10f;
    }
    float xlo = __uint_as_float(__reduce_min_sync(0xffffffffu, __float_as_uint(mxlo)));
    float xhi = __uint_as_float(__reduce_max_sync(0xffffffffu, __float_as_uint(mxhi)));

    float cx = xb[0], cy = xb[1], cz = xb[2];
    unsigned cwb = __float_as_uint(1e10f);
    int      cwi = 16*t;

    for (int j = 0; j < S_; j++) {
        float wmax_f = __uint_as_float(cwb);
        float dmx = fmaxf(fmaxf(xlo - cx, cx - xhi), 0.f);
        float dmax2 = dmx * dmx;
        unsigned nwb; int nwi;
        if (dmax2 > wmax_f * 1.0001f) {
            nwb = cwb; nwi = cwi;
        } else {
            ull ncx = pack2(-cx, -cx), ncy = pack2(-cy, -cy), ncz = pack2(-cz, -cz);
            float m = -1.0f; int mk = 0;
#pragma unroll
            for (int i = 0; i < 8; i++) {
                ull dx = add2(pxp[i], ncx);
                ull dy = add2(pyp[i], ncy);
                ull dz = add2(pzp[i], ncz);
                ull sq = mul2(dz, dz);
                fma2(sq, dy, dy);
                fma2(sq, dx, dx);
                float2 dd = unpack2(sq);
                float nd0 = fminf(dist[2*i], dd.x);
                dist[2*i] = nd0;
                if (nd0 > m) { m = nd0; mk = 2*i; }
                float nd1 = fminf(dist[2*i+1], dd.y);
                dist[2*i+1] = nd1;
                if (nd1 > m) { m = nd1; mk = 2*i+1; }
            }
            unsigned mb   = __float_as_uint(m);
            unsigned wmax = __reduce_max_sync(0xffffffffu, mb);
            unsigned bal  = __ballot_sync(0xffffffffu, mb == wmax);
            int src = __ffs(bal) - 1;
            nwb = wmax;
            nwi = __shfl_sync(0xffffffffu, 16*t + mk, src);
        }
        cwb = nwb; cwi = nwi;
        if (lane == 0) {
            cb_bits[(j & 1)*FPS_W + warp] = nwb;
            cb_idx [(j & 1)*FPS_W + warp] = nwi;
        }
        __syncthreads();
        unsigned bb   = (lane < FPS_W) ? cb_bits[(j & 1)*FPS_W + lane] : 0u;
        int      ii   = (lane < FPS_W) ? cb_idx [(j & 1)*FPS_W + lane] : 0;
        unsigned gmax = __reduce_max_sync(0xffffffffu, bb);
        unsigned bal2 = __ballot_sync(0xffffffffu, (lane < FPS_W) && (bb == gmax));
        int w2 = __ffs(bal2) - 1;
        int far = __shfl_sync(0xffffffffu, ii, w2);
        cx = ssx[far]; cy = ssy[far]; cz = ssz[far];
        if (t == 0 && j + 1 < S_) scent[j + 1] = far;
    }
    for (int s = t; s < S_; s += FPS_T) {
        int p = scent[s];
        float* o = out_xyz + ((size_t)b * S_ + s) * 3;
        o[0] = ssx[p]; o[1] = ssy[p]; o[2] = ssz[p];
    }
}

// ---------------- ball query: one warp per centroid, float4 cache --------
__global__ void ball_kernel(const float* __restrict__ new_xyz) {
    int gw = (blockIdx.x * blockDim.x + threadIdx.x) >> 5;
    int lane = threadIdx.x & 31;
    if (gw >= G_) return;
    int b = gw >> 10;
    const float4* xb4 = g_xyzw + (size_t)b * N_;
    float cx = new_xyz[gw*3+0], cy = new_xyz[gw*3+1], cz = new_xyz[gw*3+2];
    float cc = __fmaf_rn(cx, cx, __fmaf_rn(cy, cy, cz*cz));
    const float r2 = 0.04f;
    int* out = g_ball + (size_t)gw * 32;
    int count = 0;
    int firstIdx = -1;
    for (int base = 0; base < N_; base += 32) {
        int p = base + lane;
        float4 v = xb4[p];
        float dot = __fmaf_rn(cx, v.x, __fmaf_rn(cy, v.y, cz*v.z));
        float sq  = __fmaf_rn(-2.f, dot, cc) + v.w;
        bool pred = !(sq > r2);
        unsigned m = __ballot_sync(0xffffffffu, pred);
        if (firstIdx < 0 && m) firstIdx = base + __ffs(m) - 1;
        int pos = count + __popc(m & ((1u << lane) - 1u));
        if (pred && pos < 32) out[pos] = p;
        count += __popc(m);
        if (count >= 32) break;
    }
    if (count < 32) {
        if (lane >= count) out[lane] = firstIdx;
    }
}

// -------- shared gather helper: row features into smem f[128*8] (pad 8) --
__device__ __forceinline__ void gather_rows(float* f, int blockGroupBase,
                                            const float* __restrict__ xyz,
                                            const float* __restrict__ pts,
                                            const float* __restrict__ newxyz,
                                            int t) {
    if (t < 128) {
        int r = t;
        int g = blockGroupBase + (r >> 5);
        int k = r & 31;
        int b = g >> 10;
        int idx = g_ball[(size_t)g * 32 + k];
        const float* pp = xyz + ((size_t)b * N_ + idx) * 3;
        const float* cc = newxyz + (size_t)g * 3;
        f[r*8+0] = pp[0] - cc[0];
        f[r*8+1] = pp[1] - cc[1];
        f[r*8+2] = pp[2] - cc[2];
        const float* pt = pts + ((size_t)b * N_ + idx) * 3;
        f[r*8+3] = pt[0]; f[r*8+4] = pt[1]; f[r*8+5] = pt[2];
    }
}

__device__ __forceinline__ float y1_dot8(const float* f, int r,
                                         const float* wr, float bb) {
    float4 a = *(const float4*)(f + r*8);
    float2 c = *(const float2*)(f + r*8 + 4);
    float y = bb;
    y = __fmaf_rn(a.x, wr[0], y);
    y = __fmaf_rn(a.y, wr[1], y);
    y = __fmaf_rn(a.z, wr[2], y);
    y = __fmaf_rn(a.w, wr[3], y);
    y = __fmaf_rn(c.x, wr[4], y);
    y = __fmaf_rn(c.y, wr[5], y);
    return y;
}

// ---------------- stat1: gather + y1 on-the-fly, stats only (no store) ---
__global__ __launch_bounds__(256)
void stat1_kernel(const float* __restrict__ xyz, const float* __restrict__ pts,
                  const float* __restrict__ newxyz,
                  const float* __restrict__ w1, const float* __restrict__ b1) {
    __shared__ float ws[384], bs[64];
    __shared__ __align__(16) float f[128*8];
    __shared__ float red0[256], red1[256];
    int t = threadIdx.x;
    for (int e = t; e < 384; e += 256) ws[e] = w1[e];
    if (t < 64) bs[t] = b1[t];
    gather_rows(f, blockIdx.x * 4, xyz, pts, newxyz, t);
    __syncthreads();
    int c = t & 63, rb = t >> 6;
    float wr[6];
#pragma unroll
    for (int i = 0; i < 6; i++) wr[i] = ws[c*6+i];
    float bb = bs[c];
    float s = 0.f, q = 0.f;
#pragma unroll 4
    for (int i = 0; i < 32; i++) {
        float y = y1_dot8(f, rb + 4*i, wr, bb);
        s += y;
        q = __fmaf_rn(y, y, q);
    }
    red0[rb*64 + c] = s; red1[rb*64 + c] = q;
    __syncthreads();
    if (t < 64) {
        double S = (double)red0[t] + (double)red0[64+t] + (double)red0[128+t] + (double)red0[192+t];
        double Q = (double)red1[t] + (double)red1[64+t] + (double)red1[128+t] + (double)red1[192+t];
        atomicAdd(&g_sum[0][t], S);
        atomicAdd(&g_sq[0][t],  Q);
    }
}

__global__ void finalize_kernel(int l, int C,
                                const float* __restrict__ g,
                                const float* __restrict__ be) {
    int c = threadIdx.x;
    if (c < C) {
        double invn = 1.0 / (double)BSK;
        double mean = g_sum[l][c] * invn;
        double var  = g_sq[l][c] * invn - mean * mean;
        double a = (double)g[c] / sqrt(var + 1e-5);
        g_af[l][c]  = (float)a;
        g_shf[l][c] = (float)((double)be[c] - mean * a);
    }
}

// ------- layer2: 256 rows/block (2 tiles); weights loaded once -----------
#define SM2_FLOATS (64*132 + 64*64 + 128*8 + 384 + 64 + 64 + 64 + 64)
#define SM2_BYTES  (SM2_FLOATS * 4)
__global__ __launch_bounds__(256)
void layer2_kernel(const float* __restrict__ xyz, const float* __restrict__ pts,
                   const float* __restrict__ newxyz,
                   const float* __restrict__ w1, const float* __restrict__ b1,
                   const float* __restrict__ w2, const float* __restrict__ b2) {
    extern __shared__ float sm2[];
    float* zt  = sm2;            // [64][132]
    float* wt  = zt + 64*132;    // [64][64]
    float* f   = wt + 64*64;     // [128][8]
    float* ws1 = f + 128*8;
    float* bs1 = ws1 + 384;
    float* as  = bs1 + 64;
    float* sh  = as + 64;
    float* bs2 = sh + 64;
    int t = threadIdx.x;
    for (int e = t; e < 384; e += 256) ws1[e] = w1[e];
    if (t < 64) { bs1[t] = b1[t]; as[t] = g_af[0][t]; sh[t] = g_shf[0][t]; bs2[t] = b2[t]; }
    for (int e = t; e < 64*64; e += 256) { int c = e >> 6, k = e & 63; wt[k*64 + c] = w2[e]; }
    int tc = t & 7, tr = t >> 3;
    int c0 = tc * 8, r0 = tr * 4;

    for (int tile = 0; tile < 2; tile++) {
        gather_rows(f, blockIdx.x * 8 + tile * 4, xyz, pts, newxyz, t);
        __syncthreads();   // f + weights visible; prior epilogue zt reads done
        {
            int c = t & 63, rb = t >> 6;
            float wr[6];
#pragma unroll
            for (int i = 0; i < 6; i++) wr[i] = ws1[c*6+i];
            float bb = bs1[c], a = as[c], s = sh[c];
#pragma unroll 4
            for (int i = 0; i < 32; i++) {
                int r = rb + 4*i;
                float y = y1_dot8(f, r, wr, bb);
                zt[c*132 + r] = fmaxf(__fmaf_rn(y, a, s), 0.f);
            }
        }
        __syncthreads();
        ull acc[4][4];
#pragma unroll
        for (int j = 0; j < 4; j++) {
            ull bp = pack2(bs2[c0 + 2*j], bs2[c0 + 2*j + 1]);
#pragma unroll
            for (int i = 0; i < 4; i++) acc[i][j] = bp;
        }
#pragma unroll 8
        for (int k = 0; k < 64; k++) {
            float4 z  = *(const float4*)(zt + k*132 + r0);
            float4 wa = *(const float4*)(wt + k*64 + c0);
            float4 wb = *(const float4*)(wt + k*64 + c0 + 4);
            ull zp[4] = {pack2(z.x,z.x), pack2(z.y,z.y), pack2(z.z,z.z), pack2(z.w,z.w)};
            ull wp[4] = {pack2(wa.x,wa.y), pack2(wa.z,wa.w), pack2(wb.x,wb.y), pack2(wb.z,wb.w)};
#pragma unroll
            for (int i = 0; i < 4; i++)
#pragma unroll
                for (int j = 0; j < 4; j++)
                    fma2(acc[i][j], zp[i], wp[j]);
        }
        size_t rowbase = (size_t)blockIdx.x * 256 + (size_t)tile * 128;
        float ps[8], pq[8];
#pragma unroll
        for (int j = 0; j < 8; j++) { ps[j] = 0.f; pq[j] = 0.f; }
#pragma unroll
        for (int i = 0; i < 4; i++) {
            float2 v0 = unpack2(acc[i][0]), v1 = unpack2(acc[i][1]);
            float2 v2 = unpack2(acc[i][2]), v3 = unpack2(acc[i][3]);
            size_t row = rowbase + r0 + i;
            *(float4*)(g_y2 + row*64 + c0)     = make_float4(v0.x, v0.y, v1.x, v1.y);
            *(float4*)(g_y2 + row*64 + c0 + 4) = make_float4(v2.x, v2.y, v3.x, v3.y);
            float vv[8] = {v0.x, v0.y, v1.x, v1.y, v2.x, v2.y, v3.x, v3.y};
#pragma unroll
            for (int j = 0; j < 8; j++) {
                ps[j] += vv[j];
                pq[j] = __fmaf_rn(vv[j], vv[j], pq[j]);
            }
        }
        __syncthreads();                      // zt reads complete -> reuse
        float* rsum = zt;                     // [32][64]
        float* rsq  = zt + 2048;              // [32][64]
#pragma unroll
        for (int j = 0; j < 8; j++) {
            rsum[tr*64 + c0 + j] = ps[j];
            rsq [tr*64 + c0 + j] = pq[j];
        }
        __syncthreads();
        if (t < 64) {
            double S = 0.0, Q = 0.0;
            for (int i = 0; i < 32; i++) { S += (double)rsum[i*64 + t]; Q += (double)rsq[i*64 + t]; }
            atomicAdd(&g_sum[1][t], S);
            atomicAdd(&g_sq[1][t],  Q);
        }
        __syncthreads();                      // t<64 zt reads done before next tile
    }
}

// ------- layer3: 256 rows/block; weights loaded once; 2 sequential tiles -
#define SM3_FLOATS (64*132 + 64*128 + 64 + 64 + 128)
#define SM3_BYTES  (SM3_FLOATS * 4)
__global__ __launch_bounds__(256)
void layer3_kernel(const float* __restrict__ w3, const float* __restrict__ b3) {
    extern __shared__ float sm3[];
    float* zt = sm3;             // [64][132]
    float* wt = zt + 64*132;     // [64][128]
    float* as = wt + 64*128;
    float* sh = as + 64;
    float* bs = sh + 64;         // [128]
    int t = threadIdx.x;
    if (t < 64) { as[t] = g_af[1][t]; sh[t] = g_shf[1][t]; }
    if (t < 128) bs[t] = b3[t];
    for (int e = t; e < 128*64; e += 256) {   // w3 is [128][64] — load ONCE
        int c = e >> 6, k = e & 63;
        wt[k*128 + c] = w3[e];
    }
    int tc = t & 15, tr = t >> 4;
    int c0 = tc * 8, r0 = tr * 8;

    for (int tile = 0; tile < 2; tile++) {
        size_t rowbase = (size_t)blockIdx.x * 256 + (size_t)tile * 128;
        const float* yb = g_y2 + rowbase * 64;
        __syncthreads();
        for (int e4 = t; e4 < 128*16; e4 += 256) {
            int r = e4 >> 4, k0 = (e4 & 15) * 4;
            float4 v = *(const float4*)(yb + r*64 + k0);
            zt[(k0+0)*132 + r] = fmaxf(__fmaf_rn(v.x, as[k0+0], sh[k0+0]), 0.f);
            zt[(k0+1)*132 + r] = fmaxf(__fmaf_rn(v.y, as[k0+1], sh[k0+1]), 0.f);
            zt[(k0+2)*132 + r] = fmaxf(__fmaf_rn(v.z, as[k0+2], sh[k0+2]), 0.f);
            zt[(k0+3)*132 + r] = fmaxf(__fmaf_rn(v.w, as[k0+3], sh[k0+3]), 0.f);
        }
        __syncthreads();
        ull acc[8][4];
#pragma unroll
        for (int j = 0; j < 4; j++) {
            ull bp = pack2(bs[c0 + 2*j], bs[c0 + 2*j + 1]);
#pragma unroll
            for (int i = 0; i < 8; i++) acc[i][j] = bp;
        }
#pragma unroll 8
        for (int k = 0; k < 64; k++) {
            float4 za = *(const float4*)(zt + k*132 + r0);
            float4 zb = *(const float4*)(zt + k*132 + r0 + 4);
            float4 wa = *(const float4*)(wt + k*128 + c0);
            float4 wb = *(const float4*)(wt + k*128 + c0 + 4);
            ull zp[8] = {pack2(za.x,za.x), pack2(za.y,za.y), pack2(za.z,za.z), pack2(za.w,za.w),
                         pack2(zb.x,zb.x), pack2(zb.y,zb.y), pack2(zb.z,zb.z), pack2(zb.w,zb.w)};
            ull wp[4] = {pack2(wa.x,wa.y), pack2(wa.z,wa.w), pack2(wb.x,wb.y), pack2(wb.z,wb.w)};
#pragma unroll
            for (int i = 0; i < 8; i++)
#pragma unroll
                for (int j = 0; j < 4; j++)
                    fma2(acc[i][j], zp[i], wp[j]);
        }
        float cmax[8], cmin[8], csum[8], csq[8];
#pragma unroll
        for (int jp = 0; jp < 4; jp++) {
            float mA = -1e30f, mB = -1e30f, nA = 1e30f, nB = 1e30f;
            float sA = 0.f, sB = 0.f, qA = 0.f, qB = 0.f;
#pragma unroll
            for (int i = 0; i < 8; i++) {
                float2 u = unpack2(acc[i][jp]);
                mA = fmaxf(mA, u.x); nA = fminf(nA, u.x);
                sA += u.x; qA = __fmaf_rn(u.x, u.x, qA);
                mB = fmaxf(mB, u.y); nB = fminf(nB, u.y);
                sB += u.y; qB = __fmaf_rn(u.y, u.y, qB);
            }
            cmax[2*jp] = mA; cmax[2*jp+1] = mB;
            cmin[2*jp] = nA; cmin[2*jp+1] = nB;
            csum[2*jp] = sA; csum[2*jp+1] = sB;
            csq [2*jp] = qA; csq [2*jp+1] = qB;
        }
        __syncthreads();
        float* rsum = zt;                // [16][128]
        float* rsq  = zt + 2048;
        float* rmax = zt + 4096;
        float* rmin = zt + 6144;
#pragma unroll
        for (int j = 0; j < 8; j++) {
            rsum[tr*128 + c0 + j] = csum[j];
            rsq [tr*128 + c0 + j] = csq[j];
            rmax[tr*128 + c0 + j] = cmax[j];
            rmin[tr*128 + c0 + j] = cmin[j];
        }
        __syncthreads();
        if (t < 128) {
            int c = t;
            double S = 0.0, Q = 0.0;
            for (int i = 0; i < 16; i++) { S += (double)rsum[i*128 + c]; Q += (double)rsq[i*128 + c]; }
            atomicAdd(&g_sum[2][c], S);
            atomicAdd(&g_sq[2][c],  Q);
#pragma unroll
            for (int gl = 0; gl < 4; gl++) {
                float M = fmaxf(fmaxf(rmax[(4*gl+0)*128 + c], rmax[(4*gl+1)*128 + c]),
                                fmaxf(rmax[(4*gl+2)*128 + c], rmax[(4*gl+3)*128 + c]));
                float m = fminf(fminf(rmin[(4*gl+0)*128 + c], rmin[(4*gl+1)*128 + c]),
                                fminf(rmin[(4*gl+2)*128 + c], rmin[(4*gl+3)*128 + c]));
                size_t g = (size_t)blockIdx.x * 8 + (size_t)tile * 4 + gl;
                g_gmax[g*128 + c] = M;
                g_gmin[g*128 + c] = m;
            }
        }
    }
}

// ---------------- final: BN3+relu applied to group max/min ---------------
__global__ void final_kernel(float* __restrict__ out_np) {
    int i = blockIdx.x * blockDim.x + threadIdx.x;   // over G_*128
    int c = i & 127;
    float a = g_af[2][c], s = g_shf[2][c];
    float v = (a >= 0.f) ? __fmaf_rn(a, g_gmax[i], s) : __fmaf_rn(a, g_gmin[i], s);
    out_np[i] = fmaxf(v, 0.f);
}

// ---------------- launcher ----------------------------------------------
extern "C" void kernel_launch(void* const* d_in, const int* in_sizes, int n_in,
                              void* d_out, int out_size) {
    const float* xyz = (const float*)d_in[0];
    const float* pts = (const float*)d_in[1];
    const float* w1  = (const float*)d_in[2];
    const float* b1  = (const float*)d_in[3];
    const float* g1  = (const float*)d_in[4];
    const float* be1 = (const float*)d_in[5];
    const float* w2  = (const float*)d_in[6];
    const float* b2  = (const float*)d_in[7];
    const float* g2  = (const float*)d_in[8];
    const float* be2 = (const float*)d_in[9];
    const float* w3  = (const float*)d_in[10];
    const float* b3  = (const float*)d_in[11];
    const float* g3  = (const float*)d_in[12];
    const float* be3 = (const float*)d_in[13];

    float* out     = (float*)d_out;
    float* out_xyz = out;                    // (16,1024,3)
    float* out_np  = out + B_ * S_ * 3;      // (16,1024,128)

    cudaFuncSetAttribute(fps_kernel,    cudaFuncAttributeMaxDynamicSharedMemorySize, FPS_SMEM_BYTES);
    cudaFuncSetAttribute(layer2_kernel, cudaFuncAttributeMaxDynamicSharedMemorySize, SM2_BYTES);
    cudaFuncSetAttribute(layer3_kernel, cudaFuncAttributeMaxDynamicSharedMemorySize, SM3_BYTES);

    // Profiler captures launch index 3 (0-based): ball_kernel (verify float4 win).
    zero_stats_kernel<<<3, 128>>>();
    fps_kernel<<<B_, FPS_T, FPS_SMEM_BYTES>>>(xyz, out_xyz);
    prep_kernel<<<(B_*N_)/256, 256>>>(xyz);
    ball_kernel<<<(G_*32)/256, 256>>>(out_xyz);                // capture target
    stat1_kernel<<<G_/4, 256>>>(xyz, pts, out_xyz, w1, b1);
    finalize_kernel<<<1, 128>>>(0, 64, g1, be1);
    layer2_kernel<<<BSK/256, 256, SM2_BYTES>>>(xyz, pts, out_xyz, w1, b1, w2, b2);
    finalize_kernel<<<1, 128>>>(1, 64, g2, be2);
    layer3_kernel<<<BSK/256, 256, SM3_BYTES>>>(w3, b3);
    finalize_kernel<<<1, 128>>>(2, 128, g3, be3);
    final_kernel<<<(G_*128)/256, 256>>>(out_np);
}

// round 17
// speedup vs baseline: 1.0244x; 1.0244x over previous
#include <cuda_runtime.h>
#include <math.h>

#define B_   16
#define N_   8192
#define S_   1024
#define K_   32
#define G_   (B_*S_)            // 16384 groups
#define BSK  (G_*K_)            // 524288 rows

typedef unsigned long long ull;

// ---------------- device scratch (no allocations allowed) ----------------
__device__ double g_sum[3][128];
__device__ double g_sq[3][128];
__device__ float  g_af[3][128];
__device__ float  g_shf[3][128];
__device__ int    g_ball[BSK];
__device__ __align__(16) float4 g_xyzw[B_*N_];         // {x,y,z,|p|^2} 2 MB
__device__ __align__(16) float g_y2[(size_t)BSK*64];   // 128 MB
__device__ __align__(16) float g_gmax[(size_t)G_*128]; // 8 MB
__device__ __align__(16) float g_gmin[(size_t)G_*128]; // 8 MB

// ---------------- f32x2 packed helpers (IEEE .rn per lane) ---------------
__device__ __forceinline__ ull pack2(float lo, float hi) {
    ull r;
    asm("mov.b64 %0, {%1, %2};" : "=l"(r) : "f"(lo), "f"(hi));
    return r;
}
__device__ __forceinline__ void fma2(ull& d, ull a, ull b) {
    asm("fma.rn.f32x2 %0, %1, %2, %0;" : "+l"(d) : "l"(a), "l"(b));
}
__device__ __forceinline__ ull add2(ull a, ull b) {
    ull r;
    asm("add.rn.f32x2 %0, %1, %2;" : "=l"(r) : "l"(a), "l"(b));
    return r;
}
__device__ __forceinline__ ull mul2(ull a, ull b) {
    ull r;
    asm("mul.rn.f32x2 %0, %1, %2;" : "=l"(r) : "l"(a), "l"(b));
    return r;
}
__device__ __forceinline__ float2 unpack2(ull v) {
    float lo, hi;
    asm("mov.b64 {%0, %1}, %2;" : "=f"(lo), "=f"(hi) : "l"(v));
    return make_float2(lo, hi);
}

// ---------------- zero the stat accumulators (graph replay safe) ---------
__global__ void zero_stats_kernel() {
    int i = blockIdx.x * blockDim.x + threadIdx.x;
    if (i < 3*128) {
        ((double*)g_sum)[i] = 0.0;
        ((double*)g_sq)[i]  = 0.0;
    }
}

// ---------------- prep: pack {x,y,z,pp} per point ------------------------
__global__ void prep_kernel(const float* __restrict__ xyz) {
    int i = blockIdx.x * blockDim.x + threadIdx.x;    // over B_*N_
    float x = xyz[3*i], y = xyz[3*i+1], z = xyz[3*i+2];
    float pp = __fmaf_rn(x, x, __fmaf_rn(y, y, z*z));
    g_xyzw[i] = make_float4(x, y, z, pp);
}

// ---------------- noop spacer ---------------------------------------------
__global__ void noop_kernel() {}

// ---------------- FPS: x-sorted points + 32 warp-slabs, pruning ----------
// 1024 threads, 8 points/thread; warp w owns sorted [256w, 256w+256).
#define FPS_T 1024
#define FPS_W 32
#define FPS_SMEM_BYTES ((3*N_ + S_ + 2*2*FPS_W + 256) * 4)

__global__ __launch_bounds__(FPS_T, 1)
void fps_kernel(const float* __restrict__ xyz, float* __restrict__ out_xyz) {
    extern __shared__ float smf[];
    float*    ssx     = smf;
    float*    ssy     = ssx + N_;
    float*    ssz     = ssy + N_;
    int*      scent   = (int*)(ssz + N_);          // [1024]
    unsigned* cb_bits = (unsigned*)(scent + S_);   // [2][32]
    int*      cb_idx  = (int*)(cb_bits + 2*FPS_W); // [2][32]
    int*      hist    = (int*)(cb_idx + 2*FPS_W);  // [256]

    const int b = blockIdx.x, t = threadIdx.x;
    const int lane = t & 31;
    const int warp = t >> 5;
    const float* xb = xyz + (size_t)b * N_ * 3;

    // ---- counting sort by x (256 buckets) ----
    if (t < 256) hist[t] = 0;
    __syncthreads();
#pragma unroll 4
    for (int k = 0; k < 8; k++) {
        int p = 8*t + k;
        float x = xb[3*p];
        int bk = min((int)(x * 256.0f), 255);
        atomicAdd(&hist[bk], 1);
    }
    __syncthreads();
    if (t == 0) {
        int acc = 0;
        for (int i = 0; i < 256; i++) { int h = hist[i]; hist[i] = acc; acc += h; }
    }
    __syncthreads();
#pragma unroll 4
    for (int k = 0; k < 8; k++) {
        int p = 8*t + k;
        float x = xb[3*p], y = xb[3*p+1], z = xb[3*p+2];
        int bk = min((int)(x * 256.0f), 255);
        int pos = atomicAdd(&hist[bk], 1);
        ssx[pos] = x; ssy[pos] = y; ssz[pos] = z;
        if (p == 0) scent[0] = pos;
    }
    __syncthreads();

    ull pxp[4], pyp[4], pzp[4];
    float dist[8];
    float mxlo = 1e30f, mxhi = -1e30f;
#pragma unroll
    for (int i = 0; i < 4; i++) {
        int p = 8*t + 2*i;
        float x0 = ssx[p], x1 = ssx[p+1];
        pxp[i] = pack2(x0, x1);
        pyp[i] = pack2(ssy[p], ssy[p+1]);
        pzp[i] = pack2(ssz[p], ssz[p+1]);
        mxlo = fminf(mxlo, fminf(x0, x1));
        mxhi = fmaxf(mxhi, fmaxf(x0, x1));
        dist[2*i] = 1e10f; dist[2*i+1] = 1e10f;
    }
    float xlo = __uint_as_float(__reduce_min_sync(0xffffffffu, __float_as_uint(mxlo)));
    float xhi = __uint_as_float(__reduce_max_sync(0xffffffffu, __float_as_uint(mxhi)));

    float cx = xb[0], cy = xb[1], cz = xb[2];
    unsigned cwb = __float_as_uint(1e10f);
    int      cwi = 8*t;

    for (int j = 0; j < S_; j++) {
        float wmax_f = __uint_as_float(cwb);
        float dmx = fmaxf(fmaxf(xlo - cx, cx - xhi), 0.f);
        float dmax2 = dmx * dmx;
        unsigned nwb; int nwi;
        if (dmax2 > wmax_f * 1.0001f) {
            nwb = cwb; nwi = cwi;
        } else {
            ull ncx = pack2(-cx, -cx), ncy = pack2(-cy, -cy), ncz = pack2(-cz, -cz);
            float m = -1.0f; int mk = 0;
#pragma unroll
            for (int i = 0; i < 4; i++) {
                ull dx = add2(pxp[i], ncx);
                ull dy = add2(pyp[i], ncy);
                ull dz = add2(pzp[i], ncz);
                ull sq = mul2(dz, dz);
                fma2(sq, dy, dy);
                fma2(sq, dx, dx);
                float2 dd = unpack2(sq);
                float nd0 = fminf(dist[2*i], dd.x);
                dist[2*i] = nd0;
                if (nd0 > m) { m = nd0; mk = 2*i; }
                float nd1 = fminf(dist[2*i+1], dd.y);
                dist[2*i+1] = nd1;
                if (nd1 > m) { m = nd1; mk = 2*i+1; }
            }
            unsigned mb   = __float_as_uint(m);
            unsigned wmax = __reduce_max_sync(0xffffffffu, mb);
            unsigned bal  = __ballot_sync(0xffffffffu, mb == wmax);
            int src = __ffs(bal) - 1;
            nwb = wmax;
            nwi = __shfl_sync(0xffffffffu, 8*t + mk, src);
        }
        cwb = nwb; cwi = nwi;
        if (lane == 0) {
            cb_bits[(j & 1)*FPS_W + warp] = nwb;
            cb_idx [(j & 1)*FPS_W + warp] = nwi;
        }
        __syncthreads();
        unsigned bb   = cb_bits[(j & 1)*FPS_W + lane];
        int      ii   = cb_idx [(j & 1)*FPS_W + lane];
        unsigned gmax = __reduce_max_sync(0xffffffffu, bb);
        unsigned bal2 = __ballot_sync(0xffffffffu, bb == gmax);
        int w2 = __ffs(bal2) - 1;
        int far = __shfl_sync(0xffffffffu, ii, w2);
        cx = ssx[far]; cy = ssy[far]; cz = ssz[far];
        if (t == 0 && j + 1 < S_) scent[j + 1] = far;
    }
    for (int s = t; s < S_; s += FPS_T) {
        int p = scent[s];
        float* o = out_xyz + ((size_t)b * S_ + s) * 3;
        o[0] = ssx[p]; o[1] = ssy[p]; o[2] = ssz[p];
    }
}

// ---------------- ball query: warp/centroid, 64-pt chunks, MLP=2 ---------
__global__ void ball_kernel(const float* __restrict__ new_xyz) {
    int gw = (blockIdx.x * blockDim.x + threadIdx.x) >> 5;
    int lane = threadIdx.x & 31;
    if (gw >= G_) return;
    int b = gw >> 10;
    const float4* xb4 = g_xyzw + (size_t)b * N_;
    float cx = new_xyz[gw*3+0], cy = new_xyz[gw*3+1], cz = new_xyz[gw*3+2];
    float cc = __fmaf_rn(cx, cx, __fmaf_rn(cy, cy, cz*cz));
    const float r2 = 0.04f;
    int* out = g_ball + (size_t)gw * 32;
    int count = 0;
    int firstIdx = -1;
    unsigned lanemask = (1u << lane) - 1u;
    for (int base = 0; base < N_; base += 64) {
        float4 v0 = xb4[base + lane];
        float4 v1 = xb4[base + 32 + lane];
        float dot0 = __fmaf_rn(cx, v0.x, __fmaf_rn(cy, v0.y, cz*v0.z));
        float sq0  = __fmaf_rn(-2.f, dot0, cc) + v0.w;
        float dot1 = __fmaf_rn(cx, v1.x, __fmaf_rn(cy, v1.y, cz*v1.z));
        float sq1  = __fmaf_rn(-2.f, dot1, cc) + v1.w;
        bool p0 = !(sq0 > r2);
        bool p1 = !(sq1 > r2);
        unsigned m0 = __ballot_sync(0xffffffffu, p0);
        unsigned m1 = __ballot_sync(0xffffffffu, p1);
        int c0 = __popc(m0);
        int pos0 = count + __popc(m0 & lanemask);
        int pos1 = count + c0 + __popc(m1 & lanemask);
        if (p0 && pos0 < 32) out[pos0] = base + lane;
        if (p1 && pos1 < 32) out[pos1] = base + 32 + lane;
        if (firstIdx < 0 && (m0 | m1))
            firstIdx = m0 ? (base + __ffs(m0) - 1) : (base + 32 + __ffs(m1) - 1);
        count += c0 + __popc(m1);
        if (count >= 32) break;
    }
    if (count < 32) {
        if (lane >= count) out[lane] = firstIdx;
    }
}

// -------- shared gather helper: row features into smem f[128*8] (pad 8) --
__device__ __forceinline__ void gather_rows(float* f, int blockGroupBase,
                                            const float* __restrict__ xyz,
                                            const float* __restrict__ pts,
                                            const float* __restrict__ newxyz,
                                            int t) {
    if (t < 128) {
        int r = t;
        int g = blockGroupBase + (r >> 5);
        int k = r & 31;
        int b = g >> 10;
        int idx = g_ball[(size_t)g * 32 + k];
        const float* pp = xyz + ((size_t)b * N_ + idx) * 3;
        const float* cc = newxyz + (size_t)g * 3;
        f[r*8+0] = pp[0] - cc[0];
        f[r*8+1] = pp[1] - cc[1];
        f[r*8+2] = pp[2] - cc[2];
        const float* pt = pts + ((size_t)b * N_ + idx) * 3;
        f[r*8+3] = pt[0]; f[r*8+4] = pt[1]; f[r*8+5] = pt[2];
    }
}

__device__ __forceinline__ float y1_dot8(const float* f, int r,
                                         const float* wr, float bb) {
    float4 a = *(const float4*)(f + r*8);
    float2 c = *(const float2*)(f + r*8 + 4);
    float y = bb;
    y = __fmaf_rn(a.x, wr[0], y);
    y = __fmaf_rn(a.y, wr[1], y);
    y = __fmaf_rn(a.z, wr[2], y);
    y = __fmaf_rn(a.w, wr[3], y);
    y = __fmaf_rn(c.x, wr[4], y);
    y = __fmaf_rn(c.y, wr[5], y);
    return y;
}

// ---------------- stat1: gather + y1 on-the-fly, stats only (no store) ---
__global__ __launch_bounds__(256)
void stat1_kernel(const float* __restrict__ xyz, const float* __restrict__ pts,
                  const float* __restrict__ newxyz,
                  const float* __restrict__ w1, const float* __restrict__ b1) {
    __shared__ float ws[384], bs[64];
    __shared__ __align__(16) float f[128*8];
    __shared__ float red0[256], red1[256];
    int t = threadIdx.x;
    for (int e = t; e < 384; e += 256) ws[e] = w1[e];
    if (t < 64) bs[t] = b1[t];
    gather_rows(f, blockIdx.x * 4, xyz, pts, newxyz, t);
    __syncthreads();
    int c = t & 63, rb = t >> 6;
    float wr[6];
#pragma unroll
    for (int i = 0; i < 6; i++) wr[i] = ws[c*6+i];
    float bb = bs[c];
    float s = 0.f, q = 0.f;
#pragma unroll 4
    for (int i = 0; i < 32; i++) {
        float y = y1_dot8(f, rb + 4*i, wr, bb);
        s += y;
        q = __fmaf_rn(y, y, q);
    }
    red0[rb*64 + c] = s; red1[rb*64 + c] = q;
    __syncthreads();
    if (t < 64) {
        double S = (double)red0[t] + (double)red0[64+t] + (double)red0[128+t] + (double)red0[192+t];
        double Q = (double)red1[t] + (double)red1[64+t] + (double)red1[128+t] + (double)red1[192+t];
        atomicAdd(&g_sum[0][t], S);
        atomicAdd(&g_sq[0][t],  Q);
    }
}

__global__ void finalize_kernel(int l, int C,
                                const float* __restrict__ g,
                                const float* __restrict__ be) {
    int c = threadIdx.x;
    if (c < C) {
        double invn = 1.0 / (double)BSK;
        double mean = g_sum[l][c] * invn;
        double var  = g_sq[l][c] * invn - mean * mean;
        double a = (double)g[c] / sqrt(var + 1e-5);
        g_af[l][c]  = (float)a;
        g_shf[l][c] = (float)((double)be[c] - mean * a);
    }
}

// ------- layer2: 256 rows/block (2 tiles); weights loaded once -----------
#define SM2_FLOATS (64*132 + 64*64 + 128*8 + 384 + 64 + 64 + 64 + 64)
#define SM2_BYTES  (SM2_FLOATS * 4)
__global__ __launch_bounds__(256)
void layer2_kernel(const float* __restrict__ xyz, const float* __restrict__ pts,
                   const float* __restrict__ newxyz,
                   const float* __restrict__ w1, const float* __restrict__ b1,
                   const float* __restrict__ w2, const float* __restrict__ b2) {
    extern __shared__ float sm2[];
    float* zt  = sm2;            // [64][132]
    float* wt  = zt + 64*132;    // [64][64]
    float* f   = wt + 64*64;     // [128][8]
    float* ws1 = f + 128*8;
    float* bs1 = ws1 + 384;
    float* as  = bs1 + 64;
    float* sh  = as + 64;
    float* bs2 = sh + 64;
    int t = threadIdx.x;
    for (int e = t; e < 384; e += 256) ws1[e] = w1[e];
    if (t < 64) { bs1[t] = b1[t]; as[t] = g_af[0][t]; sh[t] = g_shf[0][t]; bs2[t] = b2[t]; }
    for (int e = t; e < 64*64; e += 256) { int c = e >> 6, k = e & 63; wt[k*64 + c] = w2[e]; }
    int tc = t & 7, tr = t >> 3;
    int c0 = tc * 8, r0 = tr * 4;

    for (int tile = 0; tile < 2; tile++) {
        gather_rows(f, blockIdx.x * 8 + tile * 4, xyz, pts, newxyz, t);
        __syncthreads();
        {
            int c = t & 63, rb = t >> 6;
            float wr[6];
#pragma unroll
            for (int i = 0; i < 6; i++) wr[i] = ws1[c*6+i];
            float bb = bs1[c], a = as[c], s = sh[c];
#pragma unroll 4
            for (int i = 0; i < 32; i++) {
                int r = rb + 4*i;
                float y = y1_dot8(f, r, wr, bb);
                zt[c*132 + r] = fmaxf(__fmaf_rn(y, a, s), 0.f);
            }
        }
        __syncthreads();
        ull acc[4][4];
#pragma unroll
        for (int j = 0; j < 4; j++) {
            ull bp = pack2(bs2[c0 + 2*j], bs2[c0 + 2*j + 1]);
#pragma unroll
            for (int i = 0; i < 4; i++) acc[i][j] = bp;
        }
#pragma unroll 8
        for (int k = 0; k < 64; k++) {
            float4 z  = *(const float4*)(zt + k*132 + r0);
            float4 wa = *(const float4*)(wt + k*64 + c0);
            float4 wb = *(const float4*)(wt + k*64 + c0 + 4);
            ull zp[4] = {pack2(z.x,z.x), pack2(z.y,z.y), pack2(z.z,z.z), pack2(z.w,z.w)};
            ull wp[4] = {pack2(wa.x,wa.y), pack2(wa.z,wa.w), pack2(wb.x,wb.y), pack2(wb.z,wb.w)};
#pragma unroll
            for (int i = 0; i < 4; i++)
#pragma unroll
                for (int j = 0; j < 4; j++)
                    fma2(acc[i][j], zp[i], wp[j]);
        }
        size_t rowbase = (size_t)blockIdx.x * 256 + (size_t)tile * 128;
        float ps[8], pq[8];
#pragma unroll
        for (int j = 0; j < 8; j++) { ps[j] = 0.f; pq[j] = 0.f; }
#pragma unroll
        for (int i = 0; i < 4; i++) {
            float2 v0 = unpack2(acc[i][0]), v1 = unpack2(acc[i][1]);
            float2 v2 = unpack2(acc[i][2]), v3 = unpack2(acc[i][3]);
            size_t row = rowbase + r0 + i;
            *(float4*)(g_y2 + row*64 + c0)     = make_float4(v0.x, v0.y, v1.x, v1.y);
            *(float4*)(g_y2 + row*64 + c0 + 4) = make_float4(v2.x, v2.y, v3.x, v3.y);
            float vv[8] = {v0.x, v0.y, v1.x, v1.y, v2.x, v2.y, v3.x, v3.y};
#pragma unroll
            for (int j = 0; j < 8; j++) {
                ps[j] += vv[j];
                pq[j] = __fmaf_rn(vv[j], vv[j], pq[j]);
            }
        }
        __syncthreads();
        float* rsum = zt;                     // [32][64]
        float* rsq  = zt + 2048;              // [32][64]
#pragma unroll
        for (int j = 0; j < 8; j++) {
            rsum[tr*64 + c0 + j] = ps[j];
            rsq [tr*64 + c0 + j] = pq[j];
        }
        __syncthreads();
        if (t < 64) {
            double S = 0.0, Q = 0.0;
            for (int i = 0; i < 32; i++) { S += (double)rsum[i*64 + t]; Q += (double)rsq[i*64 + t]; }
            atomicAdd(&g_sum[1][t], S);
            atomicAdd(&g_sq[1][t],  Q);
        }
        __syncthreads();
    }
}

// ------- layer3: 256 rows/block; weights loaded once; 2 sequential tiles -
#define SM3_FLOATS (64*132 + 64*128 + 64 + 64 + 128)
#define SM3_BYTES  (SM3_FLOATS * 4)
__global__ __launch_bounds__(256)
void layer3_kernel(const float* __restrict__ w3, const float* __restrict__ b3) {
    extern __shared__ float sm3[];
    float* zt = sm3;             // [64][132]
    float* wt = zt + 64*132;     // [64][128]
    float* as = wt + 64*128;
    float* sh = as + 64;
    float* bs = sh + 64;         // [128]
    int t = threadIdx.x;
    if (t < 64) { as[t] = g_af[1][t]; sh[t] = g_shf[1][t]; }
    if (t < 128) bs[t] = b3[t];
    for (int e = t; e < 128*64; e += 256) {
        int c = e >> 6, k = e & 63;
        wt[k*128 + c] = w3[e];
    }
    int tc = t & 15, tr = t >> 4;
    int c0 = tc * 8, r0 = tr * 8;

    for (int tile = 0; tile < 2; tile++) {
        size_t rowbase = (size_t)blockIdx.x * 256 + (size_t)tile * 128;
        const float* yb = g_y2 + rowbase * 64;
        __syncthreads();
        for (int e4 = t; e4 < 128*16; e4 += 256) {
            int r = e4 >> 4, k0 = (e4 & 15) * 4;
            float4 v = *(const float4*)(yb + r*64 + k0);
            zt[(k0+0)*132 + r] = fmaxf(__fmaf_rn(v.x, as[k0+0], sh[k0+0]), 0.f);
            zt[(k0+1)*132 + r] = fmaxf(__fmaf_rn(v.y, as[k0+1], sh[k0+1]), 0.f);
            zt[(k0+2)*132 + r] = fmaxf(__fmaf_rn(v.z, as[k0+2], sh[k0+2]), 0.f);
            zt[(k0+3)*132 + r] = fmaxf(__fmaf_rn(v.w, as[k0+3], sh[k0+3]), 0.f);
        }
        __syncthreads();
        ull acc[8][4];
#pragma unroll
        for (int j = 0; j < 4; j++) {
            ull bp = pack2(bs[c0 + 2*j], bs[c0 + 2*j + 1]);
#pragma unroll
            for (int i = 0; i < 8; i++) acc[i][j] = bp;
        }
#pragma unroll 8
        for (int k = 0; k < 64; k++) {
            float4 za = *(const float4*)(zt + k*132 + r0);
            float4 zb = *(const float4*)(zt + k*132 + r0 + 4);
            float4 wa = *(const float4*)(wt + k*128 + c0);
            float4 wb = *(const float4*)(wt + k*128 + c0 + 4);
            ull zp[8] = {pack2(za.x,za.x), pack2(za.y,za.y), pack2(za.z,za.z), pack2(za.w,za.w),
                         pack2(zb.x,zb.x), pack2(zb.y,zb.y), pack2(zb.z,zb.z), pack2(zb.w,zb.w)};
            ull wp[4] = {pack2(wa.x,wa.y), pack2(wa.z,wa.w), pack2(wb.x,wb.y), pack2(wb.z,wb.w)};
#pragma unroll
            for (int i = 0; i < 8; i++)
#pragma unroll
                for (int j = 0; j < 4; j++)
                    fma2(acc[i][j], zp[i], wp[j]);
        }
        float cmax[8], cmin[8], csum[8], csq[8];
#pragma unroll
        for (int jp = 0; jp < 4; jp++) {
            float mA = -1e30f, mB = -1e30f, nA = 1e30f, nB = 1e30f;
            float sA = 0.f, sB = 0.f, qA = 0.f, qB = 0.f;
#pragma unroll
            for (int i = 0; i < 8; i++) {
                float2 u = unpack2(acc[i][jp]);
                mA = fmaxf(mA, u.x); nA = fminf(nA, u.x);
                sA += u.x; qA = __fmaf_rn(u.x, u.x, qA);
                mB = fmaxf(mB, u.y); nB = fminf(nB, u.y);
                sB += u.y; qB = __fmaf_rn(u.y, u.y, qB);
            }
            cmax[2*jp] = mA; cmax[2*jp+1] = mB;
            cmin[2*jp] = nA; cmin[2*jp+1] = nB;
            csum[2*jp] = sA; csum[2*jp+1] = sB;
            csq [2*jp] = qA; csq [2*jp+1] = qB;
        }
        __syncthreads();
        float* rsum = zt;                // [16][128]
        float* rsq  = zt + 2048;
        float* rmax = zt + 4096;
        float* rmin = zt + 6144;
#pragma unroll
        for (int j = 0; j < 8; j++) {
            rsum[tr*128 + c0 + j] = csum[j];
            rsq [tr*128 + c0 + j] = csq[j];
            rmax[tr*128 + c0 + j] = cmax[j];
            rmin[tr*128 + c0 + j] = cmin[j];
        }
        __syncthreads();
        if (t < 128) {
            int c = t;
            double S = 0.0, Q = 0.0;
            for (int i = 0; i < 16; i++) { S += (double)rsum[i*128 + c]; Q += (double)rsq[i*128 + c]; }
            atomicAdd(&g_sum[2][c], S);
            atomicAdd(&g_sq[2][c],  Q);
#pragma unroll
            for (int gl = 0; gl < 4; gl++) {
                float M = fmaxf(fmaxf(rmax[(4*gl+0)*128 + c], rmax[(4*gl+1)*128 + c]),
                                fmaxf(rmax[(4*gl+2)*128 + c], rmax[(4*gl+3)*128 + c]));
                float m = fminf(fminf(rmin[(4*gl+0)*128 + c], rmin[(4*gl+1)*128 + c]),
                                fminf(rmin[(4*gl+2)*128 + c], rmin[(4*gl+3)*128 + c]));
                size_t g = (size_t)blockIdx.x * 8 + (size_t)tile * 4 + gl;
                g_gmax[g*128 + c] = M;
                g_gmin[g*128 + c] = m;
            }
        }
    }
}

// ---------------- final: BN3+relu applied to group max/min ---------------
__global__ void final_kernel(float* __restrict__ out_np) {
    int i = blockIdx.x * blockDim.x + threadIdx.x;   // over G_*128
    int c = i & 127;
    float a = g_af[2][c], s = g_shf[2][c];
    float v = (a >= 0.f) ? __fmaf_rn(a, g_gmax[i], s) : __fmaf_rn(a, g_gmin[i], s);
    out_np[i] = fmaxf(v, 0.f);
}

// ---------------- launcher ----------------------------------------------
extern "C" void kernel_launch(void* const* d_in, const int* in_sizes, int n_in,
                              void* d_out, int out_size) {
    const float* xyz = (const float*)d_in[0];
    const float* pts = (const float*)d_in[1];
    const float* w1  = (const float*)d_in[2];
    const float* b1  = (const float*)d_in[3];
    const float* g1  = (const float*)d_in[4];
    const float* be1 = (const float*)d_in[5];
    const float* w2  = (const float*)d_in[6];
    const float* b2  = (const float*)d_in[7];
    const float* g2  = (const float*)d_in[8];
    const float* be2 = (const float*)d_in[9];
    const float* w3  = (const float*)d_in[10];
    const float* b3  = (const float*)d_in[11];
    const float* g3  = (const float*)d_in[12];
    const float* be3 = (const float*)d_in[13];

    float* out     = (float*)d_out;
    float* out_xyz = out;                    // (16,1024,3)
    float* out_np  = out + B_ * S_ * 3;      // (16,1024,128)

    cudaFuncSetAttribute(fps_kernel,    cudaFuncAttributeMaxDynamicSharedMemorySize, FPS_SMEM_BYTES);
    cudaFuncSetAttribute(layer2_kernel, cudaFuncAttributeMaxDynamicSharedMemorySize, SM2_BYTES);
    cudaFuncSetAttribute(layer3_kernel, cudaFuncAttributeMaxDynamicSharedMemorySize, SM3_BYTES);

    // Profiler captures launch index 3 (0-based): fps_kernel (verify 32-slab).
    zero_stats_kernel<<<3, 128>>>();
    prep_kernel<<<(B_*N_)/256, 256>>>(xyz);
    noop_kernel<<<1, 32>>>();
    fps_kernel<<<B_, FPS_T, FPS_SMEM_BYTES>>>(xyz, out_xyz);   // capture target
    ball_kernel<<<(G_*32)/256, 256>>>(out_xyz);
    stat1_kernel<<<G_/4, 256>>>(xyz, pts, out_xyz, w1, b1);
    finalize_kernel<<<1, 128>>>(0, 64, g1, be1);
    layer2_kernel<<<BSK/256, 256, SM2_BYTES>>>(xyz, pts, out_xyz, w1, b1, w2, b2);
    finalize_kernel<<<1, 128>>>(1, 64, g2, be2);
    layer3_kernel<<<BSK/256, 256, SM3_BYTES>>>(w3, b3);
    finalize_kernel<<<1, 128>>>(2, 128, g3, be3);
    final_kernel<<<(G_*128)/256, 256>>>(out_np);
}